// round 11
// baseline (speedup 1.0000x reference)
#include <cuda_runtime.h>
#include <cuda_fp16.h>
#include <cstdint>
#include <math.h>

#define NB   8192
#define ND   128
#define MARGIN 0.2f
#define EPSL 1e-6f
#define NRB   64            // row blocks (128 rows each)
#define NCT   64            // column tiles (128 cols each)
#define NUNITS (NRB * NCT)  // 4096
#define GRID  148

// ---------------- device scratch (no allocations allowed) -------------------
__device__ float    g_a1[NB];
__device__ float2   g_cpn[NB];   // (pos? c2 : -1e30, neg? c2 : +1e30)
__device__ int      g_flag[NB];
__device__ unsigned g_pm2[NB];   // encoded running max (atomicMax)
__device__ unsigned g_nm2[NB];   // encoded running min (atomicMin)
__device__ __align__(16) __half g_e1[NB * ND];
__device__ __align__(16) __half g_e2[NB * ND];

// order-preserving float <-> uint encoding (monotone)
__device__ __forceinline__ unsigned encf(float f) {
    unsigned u = __float_as_uint(f);
    return (u & 0x80000000u) ? ~u : (u | 0x80000000u);
}
__device__ __forceinline__ float decf(unsigned u) {
    u = (u & 0x80000000u) ? (u & 0x7FFFFFFFu) : ~u;
    return __uint_as_float(u);
}

// ---------------- helpers ----------------------------------------------------
__device__ __forceinline__ uint32_t smem_u32(const void* p) {
    uint32_t a;
    asm("{ .reg .u64 t; cvta.to.shared.u64 t, %1; cvt.u32.u64 %0, t; }" : "=r"(a) : "l"(p));
    return a;
}
__device__ __forceinline__ void cp16(uint32_t saddr, const void* g) {
    asm volatile("cp.async.cg.shared.global [%0], [%1], 16;" :: "r"(saddr), "l"(g));
}
#define CP_COMMIT() asm volatile("cp.async.commit_group;" ::: "memory")
#define CP_WAIT1()  asm volatile("cp.async.wait_group 1;" ::: "memory")

#define LDSM4(r, addr) \
    asm volatile("ldmatrix.sync.aligned.m8n8.x4.shared.b16 {%0,%1,%2,%3}, [%4];" \
        : "=r"((r)[0]), "=r"((r)[1]), "=r"((r)[2]), "=r"((r)[3]) : "r"(addr))

__device__ __forceinline__ void mma16816(float* c, const uint32_t* a, uint32_t b0, uint32_t b1) {
    asm volatile("mma.sync.aligned.m16n8k16.row.col.f32.f16.f16.f32 "
        "{%0,%1,%2,%3}, {%4,%5,%6,%7}, {%8,%9}, {%0,%1,%2,%3};"
        : "+f"(c[0]), "+f"(c[1]), "+f"(c[2]), "+f"(c[3])
        : "r"(a[0]), "r"(a[1]), "r"(a[2]), "r"(a[3]), "r"(b0), "r"(b1));
}

// ---------------- prep: fp16 convert + row stats; 2 rows per warp -----------
__global__ void prep_kernel(const float* __restrict__ e1,
                            const float* __restrict__ e2,
                            const int* __restrict__ tgt) {
    int wrp = (blockIdx.x * blockDim.x + threadIdx.x) >> 5;
    int lane = threadIdx.x & 31;
    int row0 = wrp * 2;
    if (row0 >= NB) return;

    float4 a0 = ((const float4*)(e1 + (size_t)row0 * ND))[lane];
    float4 b0 = ((const float4*)(e2 + (size_t)row0 * ND))[lane];
    float4 a1 = ((const float4*)(e1 + (size_t)(row0 + 1) * ND))[lane];
    float4 b1 = ((const float4*)(e2 + (size_t)(row0 + 1) * ND))[lane];

#pragma unroll
    for (int j = 0; j < 2; ++j) {
        int row = row0 + j;
        float4 a4 = j ? a1 : a0;
        float4 b4 = j ? b1 : b0;
        __half2 ah0 = make_half2(__float2half_rn(a4.x), __float2half_rn(a4.y));
        __half2 ah1 = make_half2(__float2half_rn(a4.z), __float2half_rn(a4.w));
        __half2 bh0 = make_half2(__float2half_rn(b4.x), __float2half_rn(b4.y));
        __half2 bh1 = make_half2(__float2half_rn(b4.z), __float2half_rn(b4.w));
        ((uint2*)(g_e1 + (size_t)row * ND))[lane] =
            make_uint2(*(uint32_t*)&ah0, *(uint32_t*)&ah1);
        ((uint2*)(g_e2 + (size_t)row * ND))[lane] =
            make_uint2(*(uint32_t*)&bh0, *(uint32_t*)&bh1);

        float n1 = a4.x*a4.x + a4.y*a4.y + a4.z*a4.z + a4.w*a4.w;
        float s1 = a4.x + a4.y + a4.z + a4.w;
        float n2 = b4.x*b4.x + b4.y*b4.y + b4.z*b4.z + b4.w*b4.w;
        float s2 = b4.x + b4.y + b4.z + b4.w;
#pragma unroll
        for (int o = 16; o; o >>= 1) {
            n1 += __shfl_xor_sync(0xFFFFFFFFu, n1, o);
            s1 += __shfl_xor_sync(0xFFFFFFFFu, s1, o);
            n2 += __shfl_xor_sync(0xFFFFFFFFu, n2, o);
            s2 += __shfl_xor_sync(0xFFFFFFFFu, s2, o);
        }
        if (lane == 0) {
            g_a1[row] = n1 + 2.f * EPSL * s1 + (float)ND * EPSL * EPSL;
            float c2 = n2 - 2.f * EPSL * s2;
            int f = (tgt[row] == 1);
            g_flag[row] = f;
            g_cpn[row] = make_float2(f ? c2 : -1e30f, f ? 1e30f : c2);
            g_pm2[row] = encf(-3.402823e38f);
            g_nm2[row] = encf(3.402823e38f);
        }
    }
}

// ---------------- main kernel ------------------------------------------------
// 256 threads, 8 warps 4x2, warp = 32x64. Persistent 148 CTAs.
// k-loop uses explicit fragment double-buffering: LDSM(ks+1) issued before
// the HMMAs of ks, so LDSM latency hides under the tensor-pipe window.
#define SA      0
#define SB(s)   (32768 + (s) * 32768)
#define SC(s)   (98304 + (s) * 1024)
#define DSMEM   (98304 + 4096)

__device__ __forceinline__ void issue_tile(uint32_t sbase, int stage,
                                           int tile, int tid) {
    const uint4* gB = (const uint4*)g_e2 + (size_t)tile * 128 * 16;
#pragma unroll
    for (int i = 0; i < 8; ++i) {
        int linear = tid + 256 * i;
        int r = linear >> 4, c = linear & 15;
        cp16(sbase + SB(stage) + r * 256 + ((c ^ (r & 7)) << 4), gB + linear);
    }
    if (tid < 64)
        cp16(sbase + SC(tile & 3) + tid * 16,
             (const char*)(g_cpn + (size_t)tile * 128) + tid * 16);
}

struct LaneCtx {
    uint32_t baseA[2];
    uint32_t rowB[4];
    uint32_t sbase;
    int hA, xA, hB, xB;
    int wx, lq2;
};

__device__ __forceinline__ void load_frags(const LaneCtx& cx, uint32_t sbB, int ks,
                                           uint32_t a[2][4], uint32_t b[4][4]) {
    uint32_t cA = (uint32_t)(((2 * ks + cx.hA) ^ cx.xA) << 4);
    LDSM4(a[0], cx.baseA[0] + cA);
    LDSM4(a[1], cx.baseA[1] + cA);
    uint32_t cB = (uint32_t)(((2 * ks + cx.hB) ^ cx.xB) << 4);
#pragma unroll
    for (int p = 0; p < 4; ++p) LDSM4(b[p], sbB + cx.rowB[p] + cB);
}

__global__ __launch_bounds__(256, 1) void main_kernel() {
    extern __shared__ char sm[];
    __shared__ float s_pm[2][128], s_nm[2][128];
    const uint32_t sbase = smem_u32(sm);
    const int tid = threadIdx.x;
    const int lane = tid & 31, wid = tid >> 5;
    const int wy = wid & 3, wx = wid >> 2;

    LaneCtx cx;
    cx.sbase = sbase;
    cx.wx = wx;
    cx.lq2 = (lane & 3) * 2;
    {
        const int rA = lane & 15;
        cx.hA = lane >> 4; cx.xA = rA & 7;
#pragma unroll
        for (int mb = 0; mb < 2; ++mb)
            cx.baseA[mb] = sbase + SA + (wy * 32 + mb * 16 + rA) * 256;
        const int rB = (lane & 7) | ((lane >> 4) << 3);
        cx.hB = (lane >> 3) & 1; cx.xB = rB & 7;
#pragma unroll
        for (int p = 0; p < 4; ++p)
            cx.rowB[p] = (wx * 64 + p * 16 + rB) * 256;
    }

    int u  = (NUNITS * blockIdx.x) / GRID;
    const int u1 = (NUNITS * (blockIdx.x + 1)) / GRID;

    while (u < u1) {
        const int rb = u >> 6;
        const int ta = u & 63;
        const int tb = min(64, ta + (u1 - u));

        // ---- load A tile for this rowblock ----
        {
            const uint4* gA = (const uint4*)g_e1 + (size_t)rb * 128 * 16;
#pragma unroll
            for (int i = 0; i < 8; ++i) {
                int linear = tid + 256 * i;
                int r = linear >> 4, c = linear & 15;
                *(uint4*)(sm + SA + r * 256 + ((c ^ (r & 7)) << 4)) = gA[linear];
            }
        }

        issue_tile(sbase, ta & 1, ta, tid); CP_COMMIT();
        if (ta + 1 < tb) issue_tile(sbase, (ta + 1) & 1, ta + 1, tid);
        CP_COMMIT();

        float pm[2][2], nm[2][2];
#pragma unroll
        for (int a = 0; a < 2; ++a)
#pragma unroll
            for (int b = 0; b < 2; ++b) { pm[a][b] = -3.402823e38f; nm[a][b] = 3.402823e38f; }

#pragma unroll 1
        for (int t = ta; t < tb; ++t) {
            const int st = t & 1;
            CP_WAIT1();
            __syncthreads();

            float acc[2][8][4];
#pragma unroll
            for (int mb = 0; mb < 2; ++mb)
#pragma unroll
                for (int nb = 0; nb < 8; ++nb)
#pragma unroll
                    for (int v = 0; v < 4; ++v) acc[mb][nb][v] = 0.f;

            const uint32_t sbB = sbase + SB(st);

            // k-loop with fragment double-buffering
            uint32_t af[2][2][4], bf[2][4][4];
            load_frags(cx, sbB, 0, af[0], bf[0]);
#pragma unroll
            for (int ks = 0; ks < 8; ++ks) {
                const int cur = ks & 1, nxt = 1 - cur;
                if (ks < 7) load_frags(cx, sbB, ks + 1, af[nxt], bf[nxt]);
#pragma unroll
                for (int mb = 0; mb < 2; ++mb)
#pragma unroll
                    for (int p = 0; p < 4; ++p) {
                        mma16816(acc[mb][2 * p + 0], af[cur][mb], bf[cur][p][0], bf[cur][p][1]);
                        mma16816(acc[mb][2 * p + 1], af[cur][mb], bf[cur][p][2], bf[cur][p][3]);
                    }
            }

            // epilogue: masked running max/min of (cpn - 2*dot)
            const char* scp = sm + SC(t & 3);
#pragma unroll
            for (int nb = 0; nb < 8; ++nb) {
                int c0 = wx * 64 + nb * 8 + cx.lq2;
                float2 p0 = *(const float2*)(scp + (size_t)c0 * 8);
                float2 p1 = *(const float2*)(scp + (size_t)(c0 + 1) * 8);
#pragma unroll
                for (int mb = 0; mb < 2; ++mb) {
                    const float* A4 = acc[mb][nb];
                    pm[mb][0] = fmaxf(pm[mb][0], fmaf(-2.f, A4[0], p0.x));
                    pm[mb][0] = fmaxf(pm[mb][0], fmaf(-2.f, A4[1], p1.x));
                    pm[mb][1] = fmaxf(pm[mb][1], fmaf(-2.f, A4[2], p0.x));
                    pm[mb][1] = fmaxf(pm[mb][1], fmaf(-2.f, A4[3], p1.x));
                    nm[mb][0] = fminf(nm[mb][0], fmaf(-2.f, A4[0], p0.y));
                    nm[mb][0] = fminf(nm[mb][0], fmaf(-2.f, A4[1], p1.y));
                    nm[mb][1] = fminf(nm[mb][1], fmaf(-2.f, A4[2], p0.y));
                    nm[mb][1] = fminf(nm[mb][1], fmaf(-2.f, A4[3], p1.y));
                }
            }

            __syncthreads();
            if (t + 2 < tb) issue_tile(sbase, st, t + 2, tid);
            CP_COMMIT();
        }

        // ---- per-segment reduction + atomic merge ----
#pragma unroll
        for (int mb = 0; mb < 2; ++mb)
#pragma unroll
            for (int rh = 0; rh < 2; ++rh) {
                float p = pm[mb][rh], n = nm[mb][rh];
                p = fmaxf(p, __shfl_xor_sync(0xFFFFFFFFu, p, 1));
                p = fmaxf(p, __shfl_xor_sync(0xFFFFFFFFu, p, 2));
                n = fminf(n, __shfl_xor_sync(0xFFFFFFFFu, n, 1));
                n = fminf(n, __shfl_xor_sync(0xFFFFFFFFu, n, 2));
                if ((lane & 3) == 0) {
                    int m = wy * 32 + mb * 16 + rh * 8 + (lane >> 2);
                    s_pm[wx][m] = p;
                    s_nm[wx][m] = n;
                }
            }
        __syncthreads();
        if (tid < 128) {
            float p = fmaxf(s_pm[0][tid], s_pm[1][tid]);
            float n = fminf(s_nm[0][tid], s_nm[1][tid]);
            atomicMax(&g_pm2[rb * 128 + tid], encf(p));
            atomicMin(&g_nm2[rb * 128 + tid], encf(n));
        }
        __syncthreads();

        u += (tb - ta);
    }
}

// ---------------- finalize ---------------------------------------------------
__global__ void finalize_kernel(float* __restrict__ out) {
    __shared__ float ss[256], sw[256];
    float s = 0.f, w = 0.f;
    for (int i = threadIdx.x; i < NB; i += 256) {
        if (g_flag[i]) {
            float p = decf(g_pm2[i]);
            float n = decf(g_nm2[i]);
            float a1 = g_a1[i];
            float dp = sqrtf(fmaxf(a1 + p, 0.f));
            float dn = sqrtf(fmaxf(a1 + n, 0.f));
            s += fmaxf(dp - dn + MARGIN, 0.f);
            w += 1.f;
        }
    }
    ss[threadIdx.x] = s; sw[threadIdx.x] = w;
    __syncthreads();
#pragma unroll
    for (int o = 128; o; o >>= 1) {
        if (threadIdx.x < o) {
            ss[threadIdx.x] += ss[threadIdx.x + o];
            sw[threadIdx.x] += sw[threadIdx.x + o];
        }
        __syncthreads();
    }
    if (threadIdx.x == 0) out[0] = ss[0] / sw[0];
}

extern "C" void kernel_launch(void* const* d_in, const int* in_sizes, int n_in,
                              void* d_out, int out_size) {
    const float* e1 = (const float*)d_in[0];
    const float* e2 = (const float*)d_in[1];
    const int* tgt = (const int*)d_in[2];
    float* out = (float*)d_out;

    prep_kernel<<<NB / 16, 256>>>(e1, e2, tgt);

    cudaFuncSetAttribute(main_kernel, cudaFuncAttributeMaxDynamicSharedMemorySize, DSMEM);
    main_kernel<<<GRID, 256, DSMEM>>>();

    finalize_kernel<<<1, 256>>>(out);
}

// round 12
// speedup vs baseline: 1.5777x; 1.5777x over previous
#include <cuda_runtime.h>
#include <cuda_fp16.h>
#include <cstdint>
#include <math.h>

#define NB   8192
#define ND   128
#define MARGIN 0.2f
#define EPSL 1e-6f
#define GRID  148

// ---------------- device scratch (no allocations allowed) -------------------
__device__ float    g_a1[NB];
__device__ float    g_a1c[NB];   // compacted a1 (anchor rows only)
__device__ float2   g_cpn[NB];   // (pos? c2 : -1e30, neg? c2 : +1e30)
__device__ int      g_flag[NB];
__device__ int      g_rank[NB];  // exclusive prefix of flags
__device__ int      g_np;        // number of anchors
__device__ unsigned g_pm2[NB];   // encoded running max (atomicMax)
__device__ unsigned g_nm2[NB];   // encoded running min (atomicMin)
__device__ __align__(16) __half g_e1[NB * ND];
__device__ __align__(16) __half g_e1c[NB * ND];  // compacted anchors (zero-padded tail)
__device__ __align__(16) __half g_e2[NB * ND];

// order-preserving float <-> uint encoding (monotone)
__device__ __forceinline__ unsigned encf(float f) {
    unsigned u = __float_as_uint(f);
    return (u & 0x80000000u) ? ~u : (u | 0x80000000u);
}
__device__ __forceinline__ float decf(unsigned u) {
    u = (u & 0x80000000u) ? (u & 0x7FFFFFFFu) : ~u;
    return __uint_as_float(u);
}

// ---------------- helpers ----------------------------------------------------
__device__ __forceinline__ uint32_t smem_u32(const void* p) {
    uint32_t a;
    asm("{ .reg .u64 t; cvta.to.shared.u64 t, %1; cvt.u32.u64 %0, t; }" : "=r"(a) : "l"(p));
    return a;
}
__device__ __forceinline__ void cp16(uint32_t saddr, const void* g) {
    asm volatile("cp.async.cg.shared.global [%0], [%1], 16;" :: "r"(saddr), "l"(g));
}
#define CP_COMMIT() asm volatile("cp.async.commit_group;" ::: "memory")
#define CP_WAIT1()  asm volatile("cp.async.wait_group 1;" ::: "memory")

#define LDSM4(r, addr) \
    asm volatile("ldmatrix.sync.aligned.m8n8.x4.shared.b16 {%0,%1,%2,%3}, [%4];" \
        : "=r"((r)[0]), "=r"((r)[1]), "=r"((r)[2]), "=r"((r)[3]) : "r"(addr))

__device__ __forceinline__ void mma16816(float* c, const uint32_t* a, uint32_t b0, uint32_t b1) {
    asm volatile("mma.sync.aligned.m16n8k16.row.col.f32.f16.f16.f32 "
        "{%0,%1,%2,%3}, {%4,%5,%6,%7}, {%8,%9}, {%0,%1,%2,%3};"
        : "+f"(c[0]), "+f"(c[1]), "+f"(c[2]), "+f"(c[3])
        : "r"(a[0]), "r"(a[1]), "r"(a[2]), "r"(a[3]), "r"(b0), "r"(b1));
}

// ---------------- prep: fp16 convert + row stats; 2 rows per warp -----------
__global__ void prep_kernel(const float* __restrict__ e1,
                            const float* __restrict__ e2,
                            const int* __restrict__ tgt) {
    int wrp = (blockIdx.x * blockDim.x + threadIdx.x) >> 5;
    int lane = threadIdx.x & 31;
    int row0 = wrp * 2;
    if (row0 >= NB) return;

    float4 a0 = ((const float4*)(e1 + (size_t)row0 * ND))[lane];
    float4 b0 = ((const float4*)(e2 + (size_t)row0 * ND))[lane];
    float4 a1 = ((const float4*)(e1 + (size_t)(row0 + 1) * ND))[lane];
    float4 b1 = ((const float4*)(e2 + (size_t)(row0 + 1) * ND))[lane];

#pragma unroll
    for (int j = 0; j < 2; ++j) {
        int row = row0 + j;
        float4 a4 = j ? a1 : a0;
        float4 b4 = j ? b1 : b0;
        __half2 ah0 = make_half2(__float2half_rn(a4.x), __float2half_rn(a4.y));
        __half2 ah1 = make_half2(__float2half_rn(a4.z), __float2half_rn(a4.w));
        __half2 bh0 = make_half2(__float2half_rn(b4.x), __float2half_rn(b4.y));
        __half2 bh1 = make_half2(__float2half_rn(b4.z), __float2half_rn(b4.w));
        ((uint2*)(g_e1 + (size_t)row * ND))[lane] =
            make_uint2(*(uint32_t*)&ah0, *(uint32_t*)&ah1);
        ((uint2*)(g_e2 + (size_t)row * ND))[lane] =
            make_uint2(*(uint32_t*)&bh0, *(uint32_t*)&bh1);

        float n1 = a4.x*a4.x + a4.y*a4.y + a4.z*a4.z + a4.w*a4.w;
        float s1 = a4.x + a4.y + a4.z + a4.w;
        float n2 = b4.x*b4.x + b4.y*b4.y + b4.z*b4.z + b4.w*b4.w;
        float s2 = b4.x + b4.y + b4.z + b4.w;
#pragma unroll
        for (int o = 16; o; o >>= 1) {
            n1 += __shfl_xor_sync(0xFFFFFFFFu, n1, o);
            s1 += __shfl_xor_sync(0xFFFFFFFFu, s1, o);
            n2 += __shfl_xor_sync(0xFFFFFFFFu, n2, o);
            s2 += __shfl_xor_sync(0xFFFFFFFFu, s2, o);
        }
        if (lane == 0) {
            g_a1[row] = n1 + 2.f * EPSL * s1 + (float)ND * EPSL * EPSL;
            float c2 = n2 - 2.f * EPSL * s2;
            int f = (tgt[row] == 1);
            g_flag[row] = f;
            g_cpn[row] = make_float2(f ? c2 : -1e30f, f ? 1e30f : c2);
            g_pm2[row] = encf(-3.402823e38f);
            g_nm2[row] = encf(3.402823e38f);
        }
    }
}

// ---------------- scan: exclusive prefix of flags (1 CTA, deterministic) ----
__global__ void scan_kernel() {
    __shared__ int ps[1024];
    const int t = threadIdx.x;
    const int base = t * 8;
    int f[8], s = 0;
#pragma unroll
    for (int i = 0; i < 8; ++i) { f[i] = g_flag[base + i]; s += f[i]; }
    ps[t] = s;
    __syncthreads();
#pragma unroll
    for (int o = 1; o < 1024; o <<= 1) {
        int v = (t >= o) ? ps[t - o] : 0;
        __syncthreads();
        ps[t] += v;
        __syncthreads();
    }
    int run = ps[t] - s;   // exclusive base for this thread's 8 rows
#pragma unroll
    for (int i = 0; i < 8; ++i) { g_rank[base + i] = run; run += f[i]; }
    if (t == 1023) g_np = ps[1023];
}

// ---------------- compact: gather anchor rows into g_e1c --------------------
__global__ void compact_kernel() {
    int wrp = (blockIdx.x * blockDim.x + threadIdx.x) >> 5;
    int lane = threadIdx.x & 31;
    if (wrp >= NB) return;
    if (!g_flag[wrp]) return;
    int dst = g_rank[wrp];
    if (lane < 16)
        ((uint4*)(g_e1c + (size_t)dst * ND))[lane] =
            ((const uint4*)(g_e1 + (size_t)wrp * ND))[lane];
    else if (lane == 16)
        g_a1c[dst] = g_a1[wrp];
}

// ---------------- main kernel ------------------------------------------------
// 256 threads, 8 warps 4x2, warp = 32x64. Persistent 148 CTAs over
// nrb(dynamic) x 64 tile units. Anchor rows come from compacted g_e1c.
#define SA      0
#define SB(s)   (32768 + (s) * 32768)
#define SC(s)   (98304 + (s) * 1024)
#define DSMEM   (98304 + 4096)

__device__ __forceinline__ void issue_tile(uint32_t sbase, int stage,
                                           int tile, int tid) {
    const uint4* gB = (const uint4*)g_e2 + (size_t)tile * 128 * 16;
#pragma unroll
    for (int i = 0; i < 8; ++i) {
        int linear = tid + 256 * i;
        int r = linear >> 4, c = linear & 15;
        cp16(sbase + SB(stage) + r * 256 + ((c ^ (r & 7)) << 4), gB + linear);
    }
    if (tid < 64)
        cp16(sbase + SC(tile & 3) + tid * 16,
             (const char*)(g_cpn + (size_t)tile * 128) + tid * 16);
}

struct LaneCtx {
    uint32_t baseA[2];
    uint32_t rowB[4];
    uint32_t sbase;
    int hA, xA, hB, xB;
    int wx, lq2;
};

__device__ __forceinline__ void load_frags(const LaneCtx& cx, uint32_t sbB, int ks,
                                           uint32_t a[2][4], uint32_t b[4][4]) {
    uint32_t cA = (uint32_t)(((2 * ks + cx.hA) ^ cx.xA) << 4);
    LDSM4(a[0], cx.baseA[0] + cA);
    LDSM4(a[1], cx.baseA[1] + cA);
    uint32_t cB = (uint32_t)(((2 * ks + cx.hB) ^ cx.xB) << 4);
#pragma unroll
    for (int p = 0; p < 4; ++p) LDSM4(b[p], sbB + cx.rowB[p] + cB);
}

__global__ __launch_bounds__(256, 1) void main_kernel() {
    extern __shared__ char sm[];
    __shared__ float s_pm[2][128], s_nm[2][128];
    const uint32_t sbase = smem_u32(sm);
    const int tid = threadIdx.x;
    const int lane = tid & 31, wid = tid >> 5;
    const int wy = wid & 3, wx = wid >> 2;

    const int np = g_np;
    const int nrb = (np + 127) >> 7;
    const int nunits = nrb << 6;

    LaneCtx cx;
    cx.sbase = sbase;
    cx.wx = wx;
    cx.lq2 = (lane & 3) * 2;
    {
        const int rA = lane & 15;
        cx.hA = lane >> 4; cx.xA = rA & 7;
#pragma unroll
        for (int mb = 0; mb < 2; ++mb)
            cx.baseA[mb] = sbase + SA + (wy * 32 + mb * 16 + rA) * 256;
        const int rB = (lane & 7) | ((lane >> 4) << 3);
        cx.hB = (lane >> 3) & 1; cx.xB = rB & 7;
#pragma unroll
        for (int p = 0; p < 4; ++p)
            cx.rowB[p] = (wx * 64 + p * 16 + rB) * 256;
    }

    int u  = (nunits * (int)blockIdx.x) / GRID;
    const int u1 = (nunits * ((int)blockIdx.x + 1)) / GRID;

    while (u < u1) {
        const int rb = u >> 6;
        const int ta = u & 63;
        const int tb = min(64, ta + (u1 - u));

        // ---- load A tile (compacted anchors) for this rowblock ----
        {
            const uint4* gA = (const uint4*)g_e1c + (size_t)rb * 128 * 16;
#pragma unroll
            for (int i = 0; i < 8; ++i) {
                int linear = tid + 256 * i;
                int r = linear >> 4, c = linear & 15;
                *(uint4*)(sm + SA + r * 256 + ((c ^ (r & 7)) << 4)) = gA[linear];
            }
        }

        issue_tile(sbase, ta & 1, ta, tid); CP_COMMIT();
        if (ta + 1 < tb) issue_tile(sbase, (ta + 1) & 1, ta + 1, tid);
        CP_COMMIT();

        float pm[2][2], nm[2][2];
#pragma unroll
        for (int a = 0; a < 2; ++a)
#pragma unroll
            for (int b = 0; b < 2; ++b) { pm[a][b] = -3.402823e38f; nm[a][b] = 3.402823e38f; }

#pragma unroll 1
        for (int t = ta; t < tb; ++t) {
            const int st = t & 1;
            CP_WAIT1();
            __syncthreads();

            float acc[2][8][4];
#pragma unroll
            for (int mb = 0; mb < 2; ++mb)
#pragma unroll
                for (int nb = 0; nb < 8; ++nb)
#pragma unroll
                    for (int v = 0; v < 4; ++v) acc[mb][nb][v] = 0.f;

            const uint32_t sbB = sbase + SB(st);

            // k-loop with fragment double-buffering
            uint32_t af[2][2][4], bf[2][4][4];
            load_frags(cx, sbB, 0, af[0], bf[0]);
#pragma unroll
            for (int ks = 0; ks < 8; ++ks) {
                const int cur = ks & 1, nxt = 1 - cur;
                if (ks < 7) load_frags(cx, sbB, ks + 1, af[nxt], bf[nxt]);
#pragma unroll
                for (int mb = 0; mb < 2; ++mb)
#pragma unroll
                    for (int p = 0; p < 4; ++p) {
                        mma16816(acc[mb][2 * p + 0], af[cur][mb], bf[cur][p][0], bf[cur][p][1]);
                        mma16816(acc[mb][2 * p + 1], af[cur][mb], bf[cur][p][2], bf[cur][p][3]);
                    }
            }

            // epilogue: masked running max/min of (cpn - 2*dot)
            const char* scp = sm + SC(t & 3);
#pragma unroll
            for (int nb = 0; nb < 8; ++nb) {
                int c0 = wx * 64 + nb * 8 + cx.lq2;
                float2 p0 = *(const float2*)(scp + (size_t)c0 * 8);
                float2 p1 = *(const float2*)(scp + (size_t)(c0 + 1) * 8);
#pragma unroll
                for (int mb = 0; mb < 2; ++mb) {
                    const float* A4 = acc[mb][nb];
                    pm[mb][0] = fmaxf(pm[mb][0], fmaf(-2.f, A4[0], p0.x));
                    pm[mb][0] = fmaxf(pm[mb][0], fmaf(-2.f, A4[1], p1.x));
                    pm[mb][1] = fmaxf(pm[mb][1], fmaf(-2.f, A4[2], p0.x));
                    pm[mb][1] = fmaxf(pm[mb][1], fmaf(-2.f, A4[3], p1.x));
                    nm[mb][0] = fminf(nm[mb][0], fmaf(-2.f, A4[0], p0.y));
                    nm[mb][0] = fminf(nm[mb][0], fmaf(-2.f, A4[1], p1.y));
                    nm[mb][1] = fminf(nm[mb][1], fmaf(-2.f, A4[2], p0.y));
                    nm[mb][1] = fminf(nm[mb][1], fmaf(-2.f, A4[3], p1.y));
                }
            }

            __syncthreads();
            if (t + 2 < tb) issue_tile(sbase, st, t + 2, tid);
            CP_COMMIT();
        }

        // ---- per-segment reduction + atomic merge ----
#pragma unroll
        for (int mb = 0; mb < 2; ++mb)
#pragma unroll
            for (int rh = 0; rh < 2; ++rh) {
                float p = pm[mb][rh], n = nm[mb][rh];
                p = fmaxf(p, __shfl_xor_sync(0xFFFFFFFFu, p, 1));
                p = fmaxf(p, __shfl_xor_sync(0xFFFFFFFFu, p, 2));
                n = fminf(n, __shfl_xor_sync(0xFFFFFFFFu, n, 1));
                n = fminf(n, __shfl_xor_sync(0xFFFFFFFFu, n, 2));
                if ((lane & 3) == 0) {
                    int m = wy * 32 + mb * 16 + rh * 8 + (lane >> 2);
                    s_pm[wx][m] = p;
                    s_nm[wx][m] = n;
                }
            }
        __syncthreads();
        if (tid < 128) {
            float p = fmaxf(s_pm[0][tid], s_pm[1][tid]);
            float n = fminf(s_nm[0][tid], s_nm[1][tid]);
            atomicMax(&g_pm2[rb * 128 + tid], encf(p));
            atomicMin(&g_nm2[rb * 128 + tid], encf(n));
        }
        __syncthreads();

        u += (tb - ta);
    }
}

// ---------------- finalize ---------------------------------------------------
__global__ void finalize_kernel(float* __restrict__ out) {
    __shared__ float ss[256];
    const int np = g_np;
    float s = 0.f;
    for (int i = threadIdx.x; i < np; i += 256) {
        float p = decf(g_pm2[i]);
        float n = decf(g_nm2[i]);
        float a1 = g_a1c[i];
        float dp = sqrtf(fmaxf(a1 + p, 0.f));
        float dn = sqrtf(fmaxf(a1 + n, 0.f));
        s += fmaxf(dp - dn + MARGIN, 0.f);
    }
    ss[threadIdx.x] = s;
    __syncthreads();
#pragma unroll
    for (int o = 128; o; o >>= 1) {
        if (threadIdx.x < o) ss[threadIdx.x] += ss[threadIdx.x + o];
        __syncthreads();
    }
    if (threadIdx.x == 0) out[0] = ss[0] / (float)np;
}

extern "C" void kernel_launch(void* const* d_in, const int* in_sizes, int n_in,
                              void* d_out, int out_size) {
    const float* e1 = (const float*)d_in[0];
    const float* e2 = (const float*)d_in[1];
    const int* tgt = (const int*)d_in[2];
    float* out = (float*)d_out;

    prep_kernel<<<NB / 16, 256>>>(e1, e2, tgt);
    scan_kernel<<<1, 1024>>>();
    compact_kernel<<<NB / 8, 256>>>();

    cudaFuncSetAttribute(main_kernel, cudaFuncAttributeMaxDynamicSharedMemorySize, DSMEM);
    main_kernel<<<GRID, 256, DSMEM>>>();

    finalize_kernel<<<1, 256>>>(out);
}